// round 2
// baseline (speedup 1.0000x reference)
#include <cuda_runtime.h>
#include <cuda_fp16.h>
#include <mma.h>
#include <math.h>

using namespace nvcuda;

#define NB   8
#define NLQ  32
#define NLKV 4096
#define NH   16
#define ND   64
#define NHS  1024
#define MKV  (NB*NLKV)      /* 32768 rows of encoder */
#define MQ   (NB*NLQ)       /* 256 rows of queries   */

// ---------------- scratch (device globals; no cudaMalloc allowed) ----------
__device__ __align__(256) __half g_Xh [MKV*NHS];   // encoder in fp16 (64 MB)
__device__ __align__(256) __half g_Whk[NHS*NHS];   // Wk fp16
__device__ __align__(256) __half g_Whv[NHS*NHS];   // Wv fp16
__device__ __align__(256) float  g_Kp [MKV*NHS];   // K projected (128 MB)
__device__ __align__(256) float  g_Vp [MKV*NHS];   // V projected (128 MB)
__device__ __align__(256) float  g_Qp [MQ*NHS];    // Q projected + RoPE
__device__ __align__(256) float  g_ctx[MQ*NHS];    // attention output (pre-Wo)

// ---------------- fp32 -> fp16 conversion -----------------------------------
// dst_sel: 0 -> g_Xh, 1 -> g_Whk, 2 -> g_Whv
__global__ void cvt_f32_f16(const float* __restrict__ x, int n4, int dst_sel) {
    __half* y = (dst_sel == 0) ? g_Xh : (dst_sel == 1) ? g_Whk : g_Whv;
    int i = blockIdx.x * blockDim.x + threadIdx.x;
    if (i < n4) {
        float4 v = reinterpret_cast<const float4*>(x)[i];
        __half2 a = __floats2half2_rn(v.x, v.y);
        __half2 b = __floats2half2_rn(v.z, v.w);
        reinterpret_cast<__half2*>(y)[2*i + 0] = a;
        reinterpret_cast<__half2*>(y)[2*i + 1] = b;
    }
}

// ---------------- Q projection + RoPE (fp32, small) -------------------------
// grid: (4, 32)  -> blockIdx.x = 256-col group, blockIdx.y = 8-row group
// Positions may be int32 or int64 (JAX x64-disabled silently downgrades);
// auto-detect: view as int32, odd-indexed words all zero => int64 layout.
__global__ void __launch_bounds__(256) qproj_rope(
    const float* __restrict__ X, const float* __restrict__ W,
    const int* __restrict__ pos32)
{
    int c0 = blockIdx.x * 256;
    int r0 = blockIdx.y * 8;
    __shared__ float xs[8][NHS];
    __shared__ float qs[8][256];
    __shared__ int   is64;
    int t = threadIdx.x;

    if (t == 0) {
        int f = 0;
        // first 256 int32 words are in-bounds for either dtype (256 elements)
        for (int i = 1; i < 256; i += 2) f |= pos32[i];
        is64 = (f == 0) ? 1 : 0;
    }
    for (int i = t; i < 8 * NHS; i += 256)
        xs[i >> 10][i & 1023] = X[(size_t)(r0 + (i >> 10)) * NHS + (i & 1023)];
    __syncthreads();

    float acc[8];
#pragma unroll
    for (int r = 0; r < 8; r++) acc[r] = 0.f;

    int c = c0 + t;
    for (int k = 0; k < NHS; k++) {
        float w = W[(size_t)k * NHS + c];
#pragma unroll
        for (int r = 0; r < 8; r++) acc[r] += xs[r][k] * w;
    }
#pragma unroll
    for (int r = 0; r < 8; r++) qs[r][t] = acc[r];
    __syncthreads();

    // RoPE (query only). cos/sin index: fi = d % 32, invf = 10000^(-fi/32)
    int d  = c & 63;
    int fi = d & 31;
    float invf = (float)pow(10000.0, -(double)fi / 32.0);
#pragma unroll
    for (int r = 0; r < 8; r++) {
        int row = r0 + r;
        int p = is64 ? pos32[2 * row] : pos32[row];
        float pf = (float)p;
        float ang = pf * invf;
        float sv, cv;
        sincosf(ang, &sv, &cv);
        // partner column within this block: t ^ 32 (blocks are 256 cols, head = 64)
        float rot = (t & 32) ? qs[r][t - 32] : -qs[r][t + 32];
        g_Qp[(size_t)row * NHS + c] = qs[r][t] * cv + rot * sv;
    }
}

// ---------------- O projection (fp32, small) --------------------------------
__global__ void __launch_bounds__(256) oproj(
    const float* __restrict__ W, float* __restrict__ Y)
{
    int c0 = blockIdx.x * 256;
    int r0 = blockIdx.y * 8;
    __shared__ float xs[8][NHS];
    int t = threadIdx.x;

    for (int i = t; i < 8 * NHS; i += 256)
        xs[i >> 10][i & 1023] = g_ctx[(size_t)(r0 + (i >> 10)) * NHS + (i & 1023)];
    __syncthreads();

    float acc[8];
#pragma unroll
    for (int r = 0; r < 8; r++) acc[r] = 0.f;

    int c = c0 + t;
    for (int k = 0; k < NHS; k++) {
        float w = W[(size_t)k * NHS + c];
#pragma unroll
        for (int r = 0; r < 8; r++) acc[r] += xs[r][k] * w;
    }
#pragma unroll
    for (int r = 0; r < 8; r++)
        Y[(size_t)(r0 + r) * NHS + c] = acc[r];
}

// ---------------- K/V projections: fp16 wmma GEMM ---------------------------
// C[MKV,1024] = Xh[MKV,1024] @ W[1024,1024]; blockIdx.z: 0 -> K, 1 -> V
#define BM 128
#define BN 128
#define BK 32
__global__ void __launch_bounds__(256) gemm_kv()
{
    const __half* Bw   = blockIdx.z ? g_Whv : g_Whk;
    float*        Cout = blockIdx.z ? g_Vp  : g_Kp;
    int bn = blockIdx.x;  // 0..7
    int bm = blockIdx.y;  // 0..255

    __shared__ __align__(16) __half As[BM][BK + 8];   // 128 x 40
    __shared__ __align__(16) __half Bs[BK][BN + 8];   // 32 x 136

    int t   = threadIdx.x;
    int wid = t >> 5;
    int wm  = wid & 3;   // 0..3 -> 32-row slab
    int wn  = wid >> 2;  // 0..1 -> 64-col slab

    wmma::fragment<wmma::accumulator, 16, 16, 16, float> cf[2][4];
#pragma unroll
    for (int i = 0; i < 2; i++)
#pragma unroll
        for (int j = 0; j < 4; j++)
            wmma::fill_fragment(cf[i][j], 0.f);

    for (int k0 = 0; k0 < NHS; k0 += BK) {
        // A tile: 128x32 halfs = 512 int4 vectors
#pragma unroll
        for (int v = t; v < 512; v += 256) {
            int r = v >> 2, cc = (v & 3) * 8;
            *reinterpret_cast<int4*>(&As[r][cc]) =
                *reinterpret_cast<const int4*>(&g_Xh[(size_t)(bm * BM + r) * NHS + k0 + cc]);
        }
        // B tile: 32x128 halfs = 512 int4 vectors
#pragma unroll
        for (int v = t; v < 512; v += 256) {
            int r = v >> 4, cc = (v & 15) * 8;
            *reinterpret_cast<int4*>(&Bs[r][cc]) =
                *reinterpret_cast<const int4*>(&Bw[(size_t)(k0 + r) * NHS + bn * BN + cc]);
        }
        __syncthreads();

#pragma unroll
        for (int kk = 0; kk < BK; kk += 16) {
            wmma::fragment<wmma::matrix_a, 16, 16, 16, __half, wmma::row_major> af[2];
            wmma::fragment<wmma::matrix_b, 16, 16, 16, __half, wmma::row_major> bf[4];
#pragma unroll
            for (int i = 0; i < 2; i++)
                wmma::load_matrix_sync(af[i], &As[wm * 32 + i * 16][kk], BK + 8);
#pragma unroll
            for (int j = 0; j < 4; j++)
                wmma::load_matrix_sync(bf[j], &Bs[kk][wn * 64 + j * 16], BN + 8);
#pragma unroll
            for (int i = 0; i < 2; i++)
#pragma unroll
                for (int j = 0; j < 4; j++)
                    wmma::mma_sync(cf[i][j], af[i], bf[j], cf[i][j]);
        }
        __syncthreads();
    }

#pragma unroll
    for (int i = 0; i < 2; i++)
#pragma unroll
        for (int j = 0; j < 4; j++)
            wmma::store_matrix_sync(
                &Cout[(size_t)(bm * BM + wm * 32 + i * 16) * NHS + bn * BN + wn * 64 + j * 16],
                cf[i][j], NHS, wmma::mem_row_major);
}

// ---------------- flash attention per (b,h), fp32 ---------------------------
// grid = 128 blocks (b*16+h), 256 threads, dynamic smem
__global__ void __launch_bounds__(256) attn_kernel()
{
    extern __shared__ float sm[];
    float* Qs = sm;                   // 32 * 68
    float* Ks = Qs + 32 * 68;         // 64 * 68
    float* Vs = Ks + 64 * 68;         // 64 * 68
    float* Ps = Vs + 64 * 68;         // 32 * 65
    float* ms = Ps + 32 * 65;         // 32
    float* ss = ms + 32;              // 32

    int b = blockIdx.x >> 4;
    int h = blockIdx.x & 15;
    int t = threadIdx.x;

    // load Q (scaled by 1/sqrt(D))
    for (int i = t; i < 32 * 64; i += 256) {
        int q = i >> 6, d = i & 63;
        Qs[q * 68 + d] = g_Qp[(size_t)(b * NLQ + q) * NHS + h * ND + d] * 0.125f;
    }

    float m_run = -1e30f, l_run = 0.f;   // valid for t < 32 (row = t)
    float acc[8];
#pragma unroll
    for (int i = 0; i < 8; i++) acc[i] = 0.f;
    int qa = t >> 3;           // accumulator row
    int da = (t & 7) * 8;      // accumulator col base
    __syncthreads();

    for (int kv0 = 0; kv0 < NLKV; kv0 += 64) {
        // load K/V chunk: 2 x 64 x 64 floats = 2048 float4
        for (int v = t; v < 2048; v += 256) {
            int which = v >> 10;
            int idx = v & 1023;
            int r = idx >> 4, cc = (idx & 15) * 4;
            const float* src = (which ? g_Vp : g_Kp)
                + (size_t)(b * NLKV + kv0 + r) * NHS + h * ND + cc;
            float4 val = *reinterpret_cast<const float4*>(src);
            float* dst = (which ? Vs : Ks) + r * 68 + cc;
            *reinterpret_cast<float4*>(dst) = val;
        }
        __syncthreads();

        // scores S[32][64]
#pragma unroll
        for (int it = 0; it < 8; it++) {
            int sidx = t + it * 256;
            int q = sidx >> 6, j = sidx & 63;
            const float4* q4 = reinterpret_cast<const float4*>(&Qs[q * 68]);
            const float4* k4 = reinterpret_cast<const float4*>(&Ks[j * 68]);
            float s = 0.f;
#pragma unroll
            for (int dd = 0; dd < 16; dd++) {
                float4 a = q4[dd], bb = k4[dd];
                s += a.x * bb.x + a.y * bb.y + a.z * bb.z + a.w * bb.w;
            }
            Ps[q * 65 + j] = s;
        }
        __syncthreads();

        // per-row running max + rescale factor
        if (t < 32) {
            float mx = m_run;
            for (int j = 0; j < 64; j++) mx = fmaxf(mx, Ps[t * 65 + j]);
            float sc = __expf(m_run - mx);
            m_run = mx;
            l_run *= sc;
            ms[t] = mx;
            ss[t] = sc;
        }
        __syncthreads();

        // exponentiate in place
#pragma unroll
        for (int it = 0; it < 8; it++) {
            int sidx = t + it * 256;
            int q = sidx >> 6, j = sidx & 63;
            Ps[q * 65 + j] = __expf(Ps[q * 65 + j] - ms[q]);
        }
        __syncthreads();

        // rescale accumulators + P @ V ; also row sums
        float sc = ss[qa];
#pragma unroll
        for (int i = 0; i < 8; i++) acc[i] *= sc;
        for (int j = 0; j < 64; j++) {
            float p = Ps[qa * 65 + j];
            float4 v0 = *reinterpret_cast<const float4*>(&Vs[j * 68 + da]);
            float4 v1 = *reinterpret_cast<const float4*>(&Vs[j * 68 + da + 4]);
            acc[0] += p * v0.x; acc[1] += p * v0.y; acc[2] += p * v0.z; acc[3] += p * v0.w;
            acc[4] += p * v1.x; acc[5] += p * v1.y; acc[6] += p * v1.z; acc[7] += p * v1.w;
        }
        if (t < 32) {
            float s = 0.f;
            for (int j = 0; j < 64; j++) s += Ps[t * 65 + j];
            l_run += s;
        }
        __syncthreads();
    }

    if (t < 32) ms[t] = 1.f / l_run;
    __syncthreads();
    float inv = ms[qa];
#pragma unroll
    for (int i = 0; i < 8; i++)
        g_ctx[(size_t)(b * NLQ + qa) * NHS + h * ND + da + i] = acc[i] * inv;
}

// ---------------- launcher ---------------------------------------------------
extern "C" void kernel_launch(void* const* d_in, const int* in_sizes, int n_in,
                              void* d_out, int out_size)
{
    const float* hidden = (const float*)d_in[0];
    const float* enc    = (const float*)d_in[1];
    const int*   pos32  = (const int*)d_in[2];   // int32 OR int64 (auto-detected)
    const float* Wq     = (const float*)d_in[3];
    const float* Wk     = (const float*)d_in[4];
    const float* Wv     = (const float*)d_in[5];
    const float* Wo     = (const float*)d_in[6];
    float*       out    = (float*)d_out;

    // opt-in smem for the attention kernel (52,096 B dynamic)
    const int ATTN_SMEM = (32*68 + 64*68*2 + 32*65 + 64) * (int)sizeof(float);
    cudaFuncSetAttribute(attn_kernel, cudaFuncAttributeMaxDynamicSharedMemorySize, ATTN_SMEM);

    // 1) fp16 conversions
    {
        int n4 = (MKV * NHS) / 4;                       // 8,388,608
        cvt_f32_f16<<<(n4 + 255) / 256, 256>>>(enc, n4, 0);
        int w4 = (NHS * NHS) / 4;                       // 262,144
        cvt_f32_f16<<<(w4 + 255) / 256, 256>>>(Wk, w4, 1);
        cvt_f32_f16<<<(w4 + 255) / 256, 256>>>(Wv, w4, 2);
    }

    // 2) Q projection + RoPE (fp32)
    qproj_rope<<<dim3(4, 32), 256>>>(hidden, Wq, pos32);

    // 3) K/V projections (fp16 tensor cores, fp32 accumulate)
    gemm_kv<<<dim3(NHS / BN, MKV / BM, 2), 256>>>();

    // 4) flash attention (fp32)
    attn_kernel<<<NB * NH, 256, ATTN_SMEM>>>();

    // 5) output projection (fp32) -> d_out
    oproj<<<dim3(4, 32), 256>>>(Wo, out);
}

// round 4
// speedup vs baseline: 1.3624x; 1.3624x over previous
#include <cuda_runtime.h>
#include <cuda_fp16.h>
#include <mma.h>
#include <math.h>
#include <cstdint>

using namespace nvcuda;

#define NB   8
#define NLQ  32
#define NLKV 4096
#define NH   16
#define ND   64
#define NHS  1024
#define MKV  (NB*NLKV)      /* 32768 */
#define MQ   (NB*NLQ)       /* 256   */
#define KSPL 4              /* k-split for small projections */
#define ASPL 4              /* kv-split for attention        */

// ---------------- scratch (device globals) ----------------------------------
__device__ __align__(256) __half g_Xh  [MKV*NHS];        // encoder fp16 (64MB)
__device__ __align__(256) __half g_Whk [NHS*NHS];        // Wk fp16 [K,N]
__device__ __align__(256) __half g_Whv [NHS*NHS];        // Wv fp16 [K,N]
__device__ __align__(256) float  g_Kp  [MKV*NHS];        // K fp32 (128MB)
__device__ __align__(256) float  g_Vp  [MKV*NHS];        // V fp32 (128MB)
__device__ __align__(256) float  g_Qp  [MQ*NHS];         // Q + RoPE
__device__ __align__(256) float  g_ctx [MQ*NHS];         // attn out
__device__ __align__(256) float  g_qpart[KSPL*MQ*NHS];   // qproj partials
__device__ __align__(256) float  g_opart[KSPL*MQ*NHS];   // oproj partials
__device__ __align__(256) float  g_pacc [NB*NH*ASPL*NLQ*ND]; // attn partial O
__device__ __align__(256) float  g_pm   [NB*NH*ASPL*NLQ];
__device__ __align__(256) float  g_pl   [NB*NH*ASPL*NLQ];

// ---------------- cp.async helpers (sm_80 baseline; compiles for sm_103) -----
__device__ __forceinline__ uint32_t smem_u32(const void* p) {
    uint32_t a;
    asm("{ .reg .u64 t; cvta.to.shared.u64 t, %1; cvt.u32.u64 %0, t; }"
        : "=r"(a) : "l"(p));
    return a;
}
__device__ __forceinline__ void cp_async16(uint32_t dst, const void* src) {
    asm volatile("cp.async.cg.shared.global [%0], [%1], 16;" :: "r"(dst), "l"(src));
}
#define CP_COMMIT() asm volatile("cp.async.commit_group;" ::: "memory")
#define CP_WAIT1()  asm volatile("cp.async.wait_group 1;" ::: "memory")
#define CP_WAIT0()  asm volatile("cp.async.wait_group 0;" ::: "memory")

// ---------------- fp32 -> fp16 conversion ------------------------------------
// dst_sel: 0 -> g_Xh, 1 -> g_Whk, 2 -> g_Whv
__global__ void cvt_f32_f16(const float* __restrict__ x, int n4, int dst_sel) {
    __half* y = (dst_sel == 0) ? g_Xh : (dst_sel == 1) ? g_Whk : g_Whv;
    int i = blockIdx.x * blockDim.x + threadIdx.x;
    if (i < n4) {
        float4 v = reinterpret_cast<const float4*>(x)[i];
        reinterpret_cast<__half2*>(y)[2*i+0] = __floats2half2_rn(v.x, v.y);
        reinterpret_cast<__half2*>(y)[2*i+1] = __floats2half2_rn(v.z, v.w);
    }
}

// ---------------- qproj partial: 8 rows x 256 cols, k-range 256 per z --------
__global__ void __launch_bounds__(256) qproj_part(
    const float* __restrict__ X, const float* __restrict__ W)
{
    int c0 = blockIdx.x * 256, r0 = blockIdx.y * 8, ks = blockIdx.z;
    __shared__ float xs[8][256];
    int t = threadIdx.x;
    for (int i = t; i < 8 * 256; i += 256)
        xs[i >> 8][i & 255] = X[(size_t)(r0 + (i >> 8)) * NHS + ks * 256 + (i & 255)];
    __syncthreads();
    float acc[8];
#pragma unroll
    for (int r = 0; r < 8; r++) acc[r] = 0.f;
    int c = c0 + t;
    for (int k = 0; k < 256; k++) {
        float w = W[(size_t)(ks * 256 + k) * NHS + c];
#pragma unroll
        for (int r = 0; r < 8; r++) acc[r] += xs[r][k] * w;
    }
#pragma unroll
    for (int r = 0; r < 8; r++)
        g_qpart[((size_t)ks * MQ + r0 + r) * NHS + c] = acc[r];
}

// ---------------- reduce partials + RoPE -> g_Qp ; one block per row ---------
__global__ void __launch_bounds__(256) rope_reduce(const int* __restrict__ pos32)
{
    __shared__ float qrow[NHS];
    __shared__ int is64;
    int row = blockIdx.x, t = threadIdx.x;
    if (t == 0) {
        int f = 0;
        for (int i = 1; i < 256; i += 2) f |= pos32[i];
        is64 = (f == 0) ? 1 : 0;
    }
#pragma unroll
    for (int j = 0; j < 4; j++) {
        int c = j * 256 + t;
        float s = 0.f;
#pragma unroll
        for (int ks = 0; ks < KSPL; ks++)
            s += g_qpart[((size_t)ks * MQ + row) * NHS + c];
        qrow[c] = s;
    }
    __syncthreads();
    int p = is64 ? pos32[2 * row] : pos32[row];
    float pf = (float)p;
#pragma unroll
    for (int j = 0; j < 4; j++) {
        int c = j * 256 + t;
        int d = c & 63, fi = d & 31;
        float invf = (float)pow(10000.0, -(double)fi / 32.0);
        float sv, cv;
        sincosf(pf * invf, &sv, &cv);
        float rot = (d & 32) ? qrow[c - 32] : -qrow[c + 32];
        g_Qp[(size_t)row * NHS + c] = qrow[c] * cv + rot * sv;
    }
}

// ---------------- oproj partial (reads g_ctx) ---------------------------------
__global__ void __launch_bounds__(256) oproj_part(const float* __restrict__ W)
{
    int c0 = blockIdx.x * 256, r0 = blockIdx.y * 8, ks = blockIdx.z;
    __shared__ float xs[8][256];
    int t = threadIdx.x;
    for (int i = t; i < 8 * 256; i += 256)
        xs[i >> 8][i & 255] = g_ctx[(size_t)(r0 + (i >> 8)) * NHS + ks * 256 + (i & 255)];
    __syncthreads();
    float acc[8];
#pragma unroll
    for (int r = 0; r < 8; r++) acc[r] = 0.f;
    int c = c0 + t;
    for (int k = 0; k < 256; k++) {
        float w = W[(size_t)(ks * 256 + k) * NHS + c];
#pragma unroll
        for (int r = 0; r < 8; r++) acc[r] += xs[r][k] * w;
    }
#pragma unroll
    for (int r = 0; r < 8; r++)
        g_opart[((size_t)ks * MQ + r0 + r) * NHS + c] = acc[r];
}

__global__ void __launch_bounds__(256) oreduce(float* __restrict__ Y)
{
    int i = blockIdx.x * 256 + threadIdx.x;
    float s = 0.f;
#pragma unroll
    for (int ks = 0; ks < KSPL; ks++)
        s += g_opart[(size_t)ks * MQ * NHS + i];
    Y[i] = s;
}

// ---------------- K/V projections: wmma + cp.async double buffering ----------
// C[MKV,1024] = Xh @ W; blockIdx.z: 0 -> K, 1 -> V
#define BM 128
#define BN 128
#define BK 32
#define APAD 8     /* A row = 40 halfs (80B)   */
#define BPAD 8     /* B row = 136 halfs (272B) */
__global__ void __launch_bounds__(256) gemm_kv()
{
    const __half* Bw   = blockIdx.z ? g_Whv : g_Whk;
    float*        Cout = blockIdx.z ? g_Vp  : g_Kp;
    int bn = blockIdx.x;   // 0..7
    int bm = blockIdx.y;   // 0..255

    __shared__ __align__(16) __half As[2][BM][BK + APAD];   // 2 x 10240 B
    __shared__ __align__(16) __half Bs[2][BK][BN + BPAD];   // 2 x  8704 B

    int t   = threadIdx.x;
    int wid = t >> 5;
    int wm  = wid & 3;    // 32-row slab
    int wn  = wid >> 2;   // 64-col slab

    const __half* Abase = &g_Xh[(size_t)(bm * BM) * NHS];

    wmma::fragment<wmma::accumulator, 16, 16, 16, float> cf[2][4];
#pragma unroll
    for (int i = 0; i < 2; i++)
#pragma unroll
        for (int j = 0; j < 4; j++)
            wmma::fill_fragment(cf[i][j], 0.f);

    // stage loader: A tile 128x32 halfs (512 x 16B), B tile 32x128 halfs (512 x 16B)
    auto load_stage = [&](int it, int buf) {
        int k0 = it * BK;
#pragma unroll
        for (int ch = t; ch < 512; ch += 256) {          // A
            int r = ch >> 2, c = ch & 3;
            cp_async16(smem_u32(&As[buf][r][c * 8]),
                       Abase + (size_t)r * NHS + k0 + c * 8);
        }
#pragma unroll
        for (int ch = t; ch < 512; ch += 256) {          // B
            int r = ch >> 4, c = ch & 15;
            cp_async16(smem_u32(&Bs[buf][r][c * 8]),
                       &Bw[(size_t)(k0 + r) * NHS + bn * BN + c * 8]);
        }
        CP_COMMIT();
    };

    load_stage(0, 0);

    const int NIT = NHS / BK;   // 32
    for (int it = 0; it < NIT; it++) {
        int buf = it & 1;
        if (it + 1 < NIT) {
            load_stage(it + 1, buf ^ 1);
            CP_WAIT1();
        } else {
            CP_WAIT0();
        }
        __syncthreads();

#pragma unroll
        for (int kk = 0; kk < BK; kk += 16) {
            wmma::fragment<wmma::matrix_a, 16, 16, 16, __half, wmma::row_major> af[2];
            wmma::fragment<wmma::matrix_b, 16, 16, 16, __half, wmma::row_major> bf[4];
#pragma unroll
            for (int i = 0; i < 2; i++)
                wmma::load_matrix_sync(af[i], &As[buf][wm * 32 + i * 16][kk], BK + APAD);
#pragma unroll
            for (int j = 0; j < 4; j++)
                wmma::load_matrix_sync(bf[j], &Bs[buf][kk][wn * 64 + j * 16], BN + BPAD);
#pragma unroll
            for (int i = 0; i < 2; i++)
#pragma unroll
                for (int j = 0; j < 4; j++)
                    wmma::mma_sync(cf[i][j], af[i], bf[j], cf[i][j]);
        }
        __syncthreads();
    }

#pragma unroll
    for (int i = 0; i < 2; i++)
#pragma unroll
        for (int j = 0; j < 4; j++)
            wmma::store_matrix_sync(
                &Cout[(size_t)(bm * BM + wm * 32 + i * 16) * NHS + bn * BN + wn * 64 + j * 16],
                cf[i][j], NHS, wmma::mem_row_major);
}

// ---------------- flash attention, split-KV (fp32 K/V) ------------------------
__global__ void __launch_bounds__(256) attn_kernel()
{
    extern __shared__ float sm[];
    float* Qs = sm;                   // 32*68
    float* Ks = Qs + 32 * 68;         // 64*68
    float* Vs = Ks + 64 * 68;         // 64*68
    float* Ps = Vs + 64 * 68;         // 32*65
    float* ms = Ps + 32 * 65;         // 32
    float* ss = ms + 32;              // 32

    int bh = blockIdx.x >> 2;
    int sp = blockIdx.x & 3;
    int b = bh >> 4, h = bh & 15;
    int t = threadIdx.x;

    for (int i = t; i < 32 * 64; i += 256) {
        int q = i >> 6, d = i & 63;
        Qs[q * 68 + d] = g_Qp[(size_t)(b * NLQ + q) * NHS + h * ND + d] * 0.125f;
    }

    float m_run = -1e30f, l_run = 0.f;
    float acc[8];
#pragma unroll
    for (int i = 0; i < 8; i++) acc[i] = 0.f;
    int qa = t >> 3, da = (t & 7) * 8;
    __syncthreads();

    int kv_lo = sp * (NLKV / ASPL), kv_hi = kv_lo + NLKV / ASPL;
    for (int kv0 = kv_lo; kv0 < kv_hi; kv0 += 64) {
        for (int v = t; v < 2048; v += 256) {
            int which = v >> 10, idx = v & 1023;
            int r = idx >> 4, cc = (idx & 15) * 4;
            const float* src = (which ? g_Vp : g_Kp)
                + (size_t)(b * NLKV + kv0 + r) * NHS + h * ND + cc;
            float4 val = *reinterpret_cast<const float4*>(src);
            float* dst = (which ? Vs : Ks) + r * 68 + cc;
            *reinterpret_cast<float4*>(dst) = val;
        }
        __syncthreads();

#pragma unroll
        for (int itp = 0; itp < 8; itp++) {
            int sidx = t + itp * 256;
            int q = sidx >> 6, j = sidx & 63;
            const float4* q4 = reinterpret_cast<const float4*>(&Qs[q * 68]);
            const float4* k4 = reinterpret_cast<const float4*>(&Ks[j * 68]);
            float s = 0.f;
#pragma unroll
            for (int dd = 0; dd < 16; dd++) {
                float4 a = q4[dd], bb = k4[dd];
                s += a.x * bb.x + a.y * bb.y + a.z * bb.z + a.w * bb.w;
            }
            Ps[q * 65 + j] = s;
        }
        __syncthreads();

        if (t < 32) {
            float mx = m_run;
            for (int j = 0; j < 64; j++) mx = fmaxf(mx, Ps[t * 65 + j]);
            float sc = __expf(m_run - mx);
            m_run = mx; l_run *= sc;
            ms[t] = mx; ss[t] = sc;
        }
        __syncthreads();

#pragma unroll
        for (int itp = 0; itp < 8; itp++) {
            int sidx = t + itp * 256;
            int q = sidx >> 6, j = sidx & 63;
            Ps[q * 65 + j] = __expf(Ps[q * 65 + j] - ms[q]);
        }
        __syncthreads();

        float sc = ss[qa];
#pragma unroll
        for (int i = 0; i < 8; i++) acc[i] *= sc;
        for (int j = 0; j < 64; j++) {
            float p = Ps[qa * 65 + j];
            float4 v0 = *reinterpret_cast<const float4*>(&Vs[j * 68 + da]);
            float4 v1 = *reinterpret_cast<const float4*>(&Vs[j * 68 + da + 4]);
            acc[0] += p * v0.x; acc[1] += p * v0.y; acc[2] += p * v0.z; acc[3] += p * v0.w;
            acc[4] += p * v1.x; acc[5] += p * v1.y; acc[6] += p * v1.z; acc[7] += p * v1.w;
        }
        if (t < 32) {
            float s = 0.f;
            for (int j = 0; j < 64; j++) s += Ps[t * 65 + j];
            l_run += s;
        }
        __syncthreads();
    }

    int slot = bh * ASPL + sp;
#pragma unroll
    for (int i = 0; i < 8; i++)
        g_pacc[((size_t)slot * NLQ + qa) * ND + da + i] = acc[i];
    if (t < 32) { g_pm[slot * NLQ + t] = m_run; g_pl[slot * NLQ + t] = l_run; }
}

// ---------------- combine splits -> g_ctx --------------------------------------
__global__ void __launch_bounds__(256) attn_combine()
{
    int bh = blockIdx.x;
    int b = bh >> 4, h = bh & 15;
    int t = threadIdx.x;
    int qa = t >> 3, da = (t & 7) * 8;
    float m[ASPL], l[ASPL];
    float M = -1e30f;
#pragma unroll
    for (int s = 0; s < ASPL; s++) {
        m[s] = g_pm[(bh * ASPL + s) * NLQ + qa];
        l[s] = g_pl[(bh * ASPL + s) * NLQ + qa];
        M = fmaxf(M, m[s]);
    }
    float L = 0.f, w[ASPL];
#pragma unroll
    for (int s = 0; s < ASPL; s++) {
        w[s] = __expf(m[s] - M);
        L += w[s] * l[s];
    }
    float invL = 1.f / L;
#pragma unroll
    for (int i = 0; i < 8; i++) {
        float o = 0.f;
#pragma unroll
        for (int s = 0; s < ASPL; s++)
            o += w[s] * g_pacc[((size_t)(bh * ASPL + s) * NLQ + qa) * ND + da + i];
        g_ctx[(size_t)(b * NLQ + qa) * NHS + h * ND + da + i] = o * invL;
    }
}

// ================= launcher =====================================================
extern "C" void kernel_launch(void* const* d_in, const int* in_sizes, int n_in,
                              void* d_out, int out_size)
{
    const float* hidden = (const float*)d_in[0];
    const float* enc    = (const float*)d_in[1];
    const int*   pos32  = (const int*)d_in[2];   // int32 or int64 (auto-detect)
    const float* Wq     = (const float*)d_in[3];
    const float* Wk     = (const float*)d_in[4];
    const float* Wv     = (const float*)d_in[5];
    const float* Wo     = (const float*)d_in[6];
    float*       out    = (float*)d_out;

    const int ATTN_SMEM = (32*68 + 64*68*2 + 32*65 + 64) * (int)sizeof(float);
    cudaFuncSetAttribute(attn_kernel, cudaFuncAttributeMaxDynamicSharedMemorySize, ATTN_SMEM);

    // 1) fp16 conversions
    cvt_f32_f16<<<(MKV * NHS / 4 + 255) / 256, 256>>>(enc, MKV * NHS / 4, 0);
    cvt_f32_f16<<<(NHS * NHS / 4 + 255) / 256, 256>>>(Wk, NHS * NHS / 4, 1);
    cvt_f32_f16<<<(NHS * NHS / 4 + 255) / 256, 256>>>(Wv, NHS * NHS / 4, 2);

    // 2) Q projection (k-split) + RoPE reduce
    qproj_part<<<dim3(4, 32, KSPL), 256>>>(hidden, Wq);
    rope_reduce<<<MQ, 256>>>(pos32);

    // 3) K/V projections (wmma + cp.async pipeline)
    gemm_kv<<<dim3(NHS / BN, MKV / BM, 2), 256>>>();

    // 4) flash attention split-KV + combine
    attn_kernel<<<NB * NH * ASPL, 256, ATTN_SMEM>>>();
    attn_combine<<<NB * NH, 256>>>();

    // 5) output projection (k-split) + reduce
    oproj_part<<<dim3(4, 32, KSPL), 256>>>(Wo);
    oreduce<<<(MQ * NHS) / 256, 256>>>(out);
}

// round 5
// speedup vs baseline: 2.6386x; 1.9368x over previous
#include <cuda_runtime.h>
#include <cuda_fp16.h>
#include <mma.h>
#include <math.h>
#include <cstdint>

using namespace nvcuda;

#define NB   8
#define NLQ  32
#define NLKV 4096
#define NH   16
#define ND   64
#define NHS  1024
#define MKV  (NB*NLKV)      /* 32768 */
#define MQ   (NB*NLQ)       /* 256   */
#define MR   (NB*NH*NLQ)    /* 4096 score rows */
#define KSPL 4

// ---------------- scratch (device globals) ----------------------------------
__device__ __align__(256) __half g_Xh [MKV*NHS];         // encoder fp16 (64MB)
__device__ __align__(256) float  g_Qp [MQ*NHS];          // Q + RoPE (fp32)
__device__ __align__(256) __half g_Qt [MR*NHS];          // q~ fp16, 0.125 folded (8MB)
__device__ __align__(256) float  g_S  [(size_t)MR*NLKV]; // scores fp32 (64MB)
__device__ __align__(256) __half g_P  [(size_t)MR*NLKV]; // softmax fp16 (32MB)
__device__ __align__(256) float  g_Y  [MR*NHS];          // P@X fp32 (16MB)
__device__ __align__(256) float  g_ctx[MQ*NHS];          // per-token ctx
__device__ __align__(256) float  g_qpart[KSPL*MQ*NHS];
__device__ __align__(256) float  g_opart[KSPL*MQ*NHS];

// ---------------- cp.async helpers ------------------------------------------
__device__ __forceinline__ uint32_t smem_u32(const void* p) {
    uint32_t a;
    asm("{ .reg .u64 t; cvta.to.shared.u64 t, %1; cvt.u32.u64 %0, t; }"
        : "=r"(a) : "l"(p));
    return a;
}
__device__ __forceinline__ void cp_async16(uint32_t dst, const void* src) {
    asm volatile("cp.async.cg.shared.global [%0], [%1], 16;" :: "r"(dst), "l"(src));
}
#define CP_COMMIT() asm volatile("cp.async.commit_group;" ::: "memory")
#define CP_WAIT1()  asm volatile("cp.async.wait_group 1;" ::: "memory")
#define CP_WAIT0()  asm volatile("cp.async.wait_group 0;" ::: "memory")

// ---------------- encoder fp32 -> fp16 ---------------------------------------
__global__ void cvt_enc(const float* __restrict__ x, int n4) {
    int i = blockIdx.x * blockDim.x + threadIdx.x;
    if (i < n4) {
        float4 v = reinterpret_cast<const float4*>(x)[i];
        reinterpret_cast<__half2*>(g_Xh)[2*i+0] = __floats2half2_rn(v.x, v.y);
        reinterpret_cast<__half2*>(g_Xh)[2*i+1] = __floats2half2_rn(v.z, v.w);
    }
}

// ---------------- qproj partial ------------------------------------------------
__global__ void __launch_bounds__(256) qproj_part(
    const float* __restrict__ X, const float* __restrict__ W)
{
    int c0 = blockIdx.x * 256, r0 = blockIdx.y * 8, ks = blockIdx.z;
    __shared__ float xs[8][256];
    int t = threadIdx.x;
    for (int i = t; i < 8 * 256; i += 256)
        xs[i >> 8][i & 255] = X[(size_t)(r0 + (i >> 8)) * NHS + ks * 256 + (i & 255)];
    __syncthreads();
    float acc[8];
#pragma unroll
    for (int r = 0; r < 8; r++) acc[r] = 0.f;
    int c = c0 + t;
    for (int k = 0; k < 256; k++) {
        float w = W[(size_t)(ks * 256 + k) * NHS + c];
#pragma unroll
        for (int r = 0; r < 8; r++) acc[r] += xs[r][k] * w;
    }
#pragma unroll
    for (int r = 0; r < 8; r++)
        g_qpart[((size_t)ks * MQ + r0 + r) * NHS + c] = acc[r];
}

// ---------------- reduce + RoPE -> g_Qp ----------------------------------------
__global__ void __launch_bounds__(256) rope_reduce(const int* __restrict__ pos32)
{
    __shared__ float qrow[NHS];
    __shared__ int is64;
    int row = blockIdx.x, t = threadIdx.x;
    if (t == 0) {
        int f = 0;
        for (int i = 1; i < 256; i += 2) f |= pos32[i];
        is64 = (f == 0) ? 1 : 0;
    }
#pragma unroll
    for (int j = 0; j < 4; j++) {
        int c = j * 256 + t;
        float s = 0.f;
#pragma unroll
        for (int ks = 0; ks < KSPL; ks++)
            s += g_qpart[((size_t)ks * MQ + row) * NHS + c];
        qrow[c] = s;
    }
    __syncthreads();
    int p = is64 ? pos32[2 * row] : pos32[row];
    float pf = (float)p;
#pragma unroll
    for (int j = 0; j < 4; j++) {
        int c = j * 256 + t;
        int d = c & 63, fi = d & 31;
        float invf = (float)pow(10000.0, -(double)fi / 32.0);
        float sv, cv;
        sincosf(pf * invf, &sv, &cv);
        float rot = (d & 32) ? qrow[c - 32] : -qrow[c + 32];
        g_Qp[(size_t)row * NHS + c] = qrow[c] * cv + rot * sv;
    }
}

// ---------------- q~ = q_head @ Wk_head^T, scaled 0.125, fp16 ------------------
// block = (b*16 + h), 256 threads
__global__ void __launch_bounds__(256) qtilde(const float* __restrict__ Wk)
{
    int bh = blockIdx.x, b = bh >> 4, h = bh & 15;
    __shared__ float qs[32][65];
    __shared__ float wks[128][65];
    int t = threadIdx.x;
    for (int i = t; i < 32 * 64; i += 256) {
        int q = i >> 6, d = i & 63;
        qs[q][d] = g_Qp[(size_t)(b * NLQ + q) * NHS + h * ND + d];
    }
    int cl = t & 127, qg = t >> 7;   // qg 0..1 -> 16 q each
    for (int c0 = 0; c0 < NHS; c0 += 128) {
        __syncthreads();
        for (int i = t; i < 128 * 64; i += 256) {
            int r = i >> 6, d = i & 63;
            wks[r][d] = Wk[(size_t)(c0 + r) * NHS + h * ND + d];
        }
        __syncthreads();
        float acc[16];
#pragma unroll
        for (int j = 0; j < 16; j++) acc[j] = 0.f;
#pragma unroll
        for (int d = 0; d < 64; d++) {
            float w = wks[cl][d];
#pragma unroll
            for (int j = 0; j < 16; j++) acc[j] += qs[qg * 16 + j][d] * w;
        }
#pragma unroll
        for (int j = 0; j < 16; j++) {
            int m = bh * NLQ + qg * 16 + j;
            g_Qt[(size_t)m * NHS + c0 + cl] = __float2half_rn(acc[j] * 0.125f);
        }
    }
}

// ---------------- S = q~ @ X^T (wmma, B col-major) ------------------------------
// grid (32 n-tiles, 4 m-tiles, 8 b), block 256
#define BM 128
#define BN 128
#define BK 32
#define APAD 8
__global__ void __launch_bounds__(256) sgemm()
{
    int b = blockIdx.z;
    int n0 = blockIdx.x * BN, m0 = blockIdx.y * BM;
    const __half* Ab = g_Qt + (size_t)b * 512 * NHS;
    const __half* Xb = g_Xh + (size_t)b * NLKV * NHS;
    float* Cb = g_S + (size_t)b * 512 * NLKV;

    __shared__ __align__(16) __half As[2][BM][BK + APAD];
    __shared__ __align__(16) __half Bs[2][BN][BK + APAD];   // Bs[n][k] (col-major tile)

    int t = threadIdx.x, wid = t >> 5;
    int wm = wid & 3, wn = wid >> 2;

    wmma::fragment<wmma::accumulator, 16, 16, 16, float> cf[2][4];
#pragma unroll
    for (int i = 0; i < 2; i++)
#pragma unroll
        for (int j = 0; j < 4; j++) wmma::fill_fragment(cf[i][j], 0.f);

    auto load_stage = [&](int it, int buf) {
        int k0 = it * BK;
#pragma unroll
        for (int ch = t; ch < 512; ch += 256) {     // A: 128 rows x 4 chunks
            int r = ch >> 2, c = ch & 3;
            cp_async16(smem_u32(&As[buf][r][c * 8]),
                       &Ab[(size_t)(m0 + r) * NHS + k0 + c * 8]);
        }
#pragma unroll
        for (int ch = t; ch < 512; ch += 256) {     // B: 128 kv-rows x 4 chunks
            int r = ch >> 2, c = ch & 3;
            cp_async16(smem_u32(&Bs[buf][r][c * 8]),
                       &Xb[(size_t)(n0 + r) * NHS + k0 + c * 8]);
        }
        CP_COMMIT();
    };

    load_stage(0, 0);
    const int NIT = NHS / BK;   // 32
    for (int it = 0; it < NIT; it++) {
        int buf = it & 1;
        if (it + 1 < NIT) { load_stage(it + 1, buf ^ 1); CP_WAIT1(); }
        else              { CP_WAIT0(); }
        __syncthreads();
#pragma unroll
        for (int kk = 0; kk < BK; kk += 16) {
            wmma::fragment<wmma::matrix_a, 16, 16, 16, __half, wmma::row_major> af[2];
            wmma::fragment<wmma::matrix_b, 16, 16, 16, __half, wmma::col_major> bf[4];
#pragma unroll
            for (int i = 0; i < 2; i++)
                wmma::load_matrix_sync(af[i], &As[buf][wm * 32 + i * 16][kk], BK + APAD);
#pragma unroll
            for (int j = 0; j < 4; j++)
                wmma::load_matrix_sync(bf[j], &Bs[buf][wn * 64 + j * 16][kk], BK + APAD);
#pragma unroll
            for (int i = 0; i < 2; i++)
#pragma unroll
                for (int j = 0; j < 4; j++)
                    wmma::mma_sync(cf[i][j], af[i], bf[j], cf[i][j]);
        }
        __syncthreads();
    }
#pragma unroll
    for (int i = 0; i < 2; i++)
#pragma unroll
        for (int j = 0; j < 4; j++)
            wmma::store_matrix_sync(
                &Cb[(size_t)(m0 + wm * 32 + i * 16) * NLKV + n0 + wn * 64 + j * 16],
                cf[i][j], NLKV, wmma::mem_row_major);
}

// ---------------- softmax rows of 4096 -> fp16 P --------------------------------
__global__ void __launch_bounds__(256) softmax_rows()
{
    size_t m = blockIdx.x;
    const float* row = g_S + m * NLKV;
    __half* prow = g_P + m * NLKV;
    int t = threadIdx.x;
    __shared__ float red[8];

    float x[16];
    float mx = -1e30f;
#pragma unroll
    for (int i = 0; i < 16; i++) {
        x[i] = row[i * 256 + t];
        mx = fmaxf(mx, x[i]);
    }
#pragma unroll
    for (int o = 16; o > 0; o >>= 1)
        mx = fmaxf(mx, __shfl_xor_sync(0xffffffffu, mx, o));
    if ((t & 31) == 0) red[t >> 5] = mx;
    __syncthreads();
    if (t < 8) {
        float v = red[t];
#pragma unroll
        for (int o = 4; o > 0; o >>= 1) v = fmaxf(v, __shfl_xor_sync(0xffu, v, o));
        red[t] = v;
    }
    __syncthreads();
    mx = red[0];

    float s = 0.f;
#pragma unroll
    for (int i = 0; i < 16; i++) {
        x[i] = __expf(x[i] - mx);
        s += x[i];
    }
#pragma unroll
    for (int o = 16; o > 0; o >>= 1)
        s += __shfl_xor_sync(0xffffffffu, s, o);
    __syncthreads();
    if ((t & 31) == 0) red[t >> 5] = s;
    __syncthreads();
    if (t < 8) {
        float v = red[t];
#pragma unroll
        for (int o = 4; o > 0; o >>= 1) v += __shfl_xor_sync(0xffu, v, o);
        red[t] = v;
    }
    __syncthreads();
    float inv = 1.f / red[0];
#pragma unroll
    for (int i = 0; i < 16; i++)
        prow[i * 256 + t] = __float2half_rn(x[i] * inv);
}

// ---------------- Y = P @ X (wmma, B row-major) ---------------------------------
// grid (8 n-tiles, 4 m-tiles, 8 b), block 256
#define BPAD 8
__global__ void __launch_bounds__(256) ygemm()
{
    int b = blockIdx.z;
    int n0 = blockIdx.x * BN, m0 = blockIdx.y * BM;
    const __half* Ab = g_P + (size_t)b * 512 * NLKV;
    const __half* Xb = g_Xh + (size_t)b * NLKV * NHS;
    float* Cb = g_Y + (size_t)b * 512 * NHS;

    __shared__ __align__(16) __half As[2][BM][BK + APAD];
    __shared__ __align__(16) __half Bs[2][BK][BN + BPAD];

    int t = threadIdx.x, wid = t >> 5;
    int wm = wid & 3, wn = wid >> 2;

    wmma::fragment<wmma::accumulator, 16, 16, 16, float> cf[2][4];
#pragma unroll
    for (int i = 0; i < 2; i++)
#pragma unroll
        for (int j = 0; j < 4; j++) wmma::fill_fragment(cf[i][j], 0.f);

    auto load_stage = [&](int it, int buf) {
        int k0 = it * BK;
#pragma unroll
        for (int ch = t; ch < 512; ch += 256) {     // A (P): 128 rows x 4 chunks
            int r = ch >> 2, c = ch & 3;
            cp_async16(smem_u32(&As[buf][r][c * 8]),
                       &Ab[(size_t)(m0 + r) * NLKV + k0 + c * 8]);
        }
#pragma unroll
        for (int ch = t; ch < 512; ch += 256) {     // B (X): 32 rows x 16 chunks
            int r = ch >> 4, c = ch & 15;
            cp_async16(smem_u32(&Bs[buf][r][c * 8]),
                       &Xb[(size_t)(k0 + r) * NHS + n0 + c * 8]);
        }
        CP_COMMIT();
    };

    load_stage(0, 0);
    const int NIT = NLKV / BK;   // 128
    for (int it = 0; it < NIT; it++) {
        int buf = it & 1;
        if (it + 1 < NIT) { load_stage(it + 1, buf ^ 1); CP_WAIT1(); }
        else              { CP_WAIT0(); }
        __syncthreads();
#pragma unroll
        for (int kk = 0; kk < BK; kk += 16) {
            wmma::fragment<wmma::matrix_a, 16, 16, 16, __half, wmma::row_major> af[2];
            wmma::fragment<wmma::matrix_b, 16, 16, 16, __half, wmma::row_major> bf[4];
#pragma unroll
            for (int i = 0; i < 2; i++)
                wmma::load_matrix_sync(af[i], &As[buf][wm * 32 + i * 16][kk], BK + APAD);
#pragma unroll
            for (int j = 0; j < 4; j++)
                wmma::load_matrix_sync(bf[j], &Bs[buf][kk][wn * 64 + j * 16], BN + BPAD);
#pragma unroll
            for (int i = 0; i < 2; i++)
#pragma unroll
                for (int j = 0; j < 4; j++)
                    wmma::mma_sync(cf[i][j], af[i], bf[j], cf[i][j]);
        }
        __syncthreads();
    }
#pragma unroll
    for (int i = 0; i < 2; i++)
#pragma unroll
        for (int j = 0; j < 4; j++)
            wmma::store_matrix_sync(
                &Cb[(size_t)(m0 + wm * 32 + i * 16) * NHS + n0 + wn * 64 + j * 16],
                cf[i][j], NHS, wmma::mem_row_major);
}

// ---------------- ctx_head = Y_head @ Wv_head -----------------------------------
// block = (b*16 + h), 256 threads
__global__ void __launch_bounds__(256) vproj(const float* __restrict__ Wv)
{
    int bh = blockIdx.x, b = bh >> 4, h = bh & 15;
    __shared__ float wvs[128][65];
    __shared__ float ys[32][129];
    int t = threadIdx.x;
    int d = t & 63, qg = t >> 6;   // qg 0..3 -> 8 q each
    float acc[8];
#pragma unroll
    for (int j = 0; j < 8; j++) acc[j] = 0.f;

    for (int c0 = 0; c0 < NHS; c0 += 128) {
        __syncthreads();
        for (int i = t; i < 128 * 64; i += 256) {
            int r = i >> 6, dd = i & 63;
            wvs[r][dd] = Wv[(size_t)(c0 + r) * NHS + h * ND + dd];
        }
        for (int i = t; i < 32 * 128; i += 256) {
            int q = i >> 7, cl = i & 127;
            ys[q][cl] = g_Y[(size_t)(bh * NLQ + q) * NHS + c0 + cl];
        }
        __syncthreads();
#pragma unroll 4
        for (int c = 0; c < 128; c++) {
            float w = wvs[c][d];
#pragma unroll
            for (int j = 0; j < 8; j++) acc[j] += ys[qg * 8 + j][c] * w;
        }
    }
#pragma unroll
    for (int j = 0; j < 8; j++)
        g_ctx[(size_t)(b * NLQ + qg * 8 + j) * NHS + h * ND + d] = acc[j];
}

// ---------------- oproj partial + reduce -----------------------------------------
__global__ void __launch_bounds__(256) oproj_part(const float* __restrict__ W)
{
    int c0 = blockIdx.x * 256, r0 = blockIdx.y * 8, ks = blockIdx.z;
    __shared__ float xs[8][256];
    int t = threadIdx.x;
    for (int i = t; i < 8 * 256; i += 256)
        xs[i >> 8][i & 255] = g_ctx[(size_t)(r0 + (i >> 8)) * NHS + ks * 256 + (i & 255)];
    __syncthreads();
    float acc[8];
#pragma unroll
    for (int r = 0; r < 8; r++) acc[r] = 0.f;
    int c = c0 + t;
    for (int k = 0; k < 256; k++) {
        float w = W[(size_t)(ks * 256 + k) * NHS + c];
#pragma unroll
        for (int r = 0; r < 8; r++) acc[r] += xs[r][k] * w;
    }
#pragma unroll
    for (int r = 0; r < 8; r++)
        g_opart[((size_t)ks * MQ + r0 + r) * NHS + c] = acc[r];
}

__global__ void __launch_bounds__(256) oreduce(float* __restrict__ Y)
{
    int i = blockIdx.x * 256 + threadIdx.x;
    float s = 0.f;
#pragma unroll
    for (int ks = 0; ks < KSPL; ks++)
        s += g_opart[(size_t)ks * MQ * NHS + i];
    Y[i] = s;
}

// ================= launcher =======================================================
extern "C" void kernel_launch(void* const* d_in, const int* in_sizes, int n_in,
                              void* d_out, int out_size)
{
    const float* hidden = (const float*)d_in[0];
    const float* enc    = (const float*)d_in[1];
    const int*   pos32  = (const int*)d_in[2];
    const float* Wq     = (const float*)d_in[3];
    const float* Wk     = (const float*)d_in[4];
    const float* Wv     = (const float*)d_in[5];
    const float* Wo     = (const float*)d_in[6];
    float*       out    = (float*)d_out;

    // encoder to fp16
    cvt_enc<<<(MKV * NHS / 4 + 255) / 256, 256>>>(enc, MKV * NHS / 4);

    // Q projection + RoPE
    qproj_part<<<dim3(4, 32, KSPL), 256>>>(hidden, Wq);
    rope_reduce<<<MQ, 256>>>(pos32);

    // fold Wk into q
    qtilde<<<NB * NH, 256>>>(Wk);

    // S = q~ @ X^T
    sgemm<<<dim3(NLKV / BN, 4, NB), 256>>>();

    // softmax
    softmax_rows<<<MR, 256>>>();

    // Y = P @ X
    ygemm<<<dim3(NHS / BN, 4, NB), 256>>>();

    // fold Wv
    vproj<<<NB * NH, 256>>>(Wv);

    // output projection
    oproj_part<<<dim3(4, 32, KSPL), 256>>>(Wo);
    oreduce<<<(MQ * NHS) / 256, 256>>>(out);
}

// round 6
// speedup vs baseline: 2.8488x; 1.0797x over previous
#include <cuda_runtime.h>
#include <cuda_fp16.h>
#include <mma.h>
#include <math.h>
#include <cstdint>

using namespace nvcuda;

#define NB   8
#define NLQ  32
#define NLKV 4096
#define NH   16
#define ND   64
#define NHS  1024
#define MKV  (NB*NLKV)      /* 32768 */
#define MQ   (NB*NLQ)       /* 256   */
#define MR   (NB*NH*NLQ)    /* 4096 score rows */
#define KSPL 4

// ---------------- scratch (device globals) ----------------------------------
__device__ __align__(256) __half g_Xh [MKV*NHS];         // encoder fp16 (64MB)
__device__ __align__(256) float  g_Qp [MQ*NHS];          // Q + RoPE (fp32)
__device__ __align__(256) __half g_Qt [MR*NHS];          // q~ fp16, 0.125 folded
__device__ __align__(256) float  g_S  [(size_t)MR*NLKV]; // scores fp32 (64MB)
__device__ __align__(256) __half g_P  [(size_t)MR*NLKV]; // softmax fp16 (32MB)
__device__ __align__(256) float  g_Y  [MR*NHS];          // P@X fp32 (16MB)
__device__ __align__(256) float  g_qpart[KSPL*MQ*NHS];   // qproj partials, later vproj partials
__device__ __align__(256) float  g_opart[KSPL*MQ*NHS];   // oproj partials

// ---------------- cp.async helpers ------------------------------------------
__device__ __forceinline__ uint32_t smem_u32(const void* p) {
    uint32_t a;
    asm("{ .reg .u64 t; cvta.to.shared.u64 t, %1; cvt.u32.u64 %0, t; }"
        : "=r"(a) : "l"(p));
    return a;
}
__device__ __forceinline__ void cp_async16(uint32_t dst, const void* src) {
    asm volatile("cp.async.cg.shared.global [%0], [%1], 16;" :: "r"(dst), "l"(src));
}
#define CP_COMMIT() asm volatile("cp.async.commit_group;" ::: "memory")
#define CP_WAIT1()  asm volatile("cp.async.wait_group 1;" ::: "memory")
#define CP_WAIT0()  asm volatile("cp.async.wait_group 0;" ::: "memory")

// ---------------- encoder fp32 -> fp16 ---------------------------------------
__global__ void cvt_enc(const float* __restrict__ x, int n4) {
    int i = blockIdx.x * blockDim.x + threadIdx.x;
    if (i < n4) {
        float4 v = reinterpret_cast<const float4*>(x)[i];
        reinterpret_cast<__half2*>(g_Xh)[2*i+0] = __floats2half2_rn(v.x, v.y);
        reinterpret_cast<__half2*>(g_Xh)[2*i+1] = __floats2half2_rn(v.z, v.w);
    }
}

// ---------------- qproj partial: 32 rows x 256 cols, k-range 256 per z --------
// grid (4, 8, 4), 256 threads
__global__ void __launch_bounds__(256) qproj_part(
    const float* __restrict__ X, const float* __restrict__ W)
{
    int c0 = blockIdx.x * 256, r0 = blockIdx.y * 32, ks = blockIdx.z;
    __shared__ float xs[32][256];
    int t = threadIdx.x;
    for (int i = t; i < 32 * 256; i += 256)
        xs[i >> 8][i & 255] = X[(size_t)(r0 + (i >> 8)) * NHS + ks * 256 + (i & 255)];
    __syncthreads();
    float acc[32];
#pragma unroll
    for (int r = 0; r < 32; r++) acc[r] = 0.f;
    int c = c0 + t;
    const float* Wc = W + (size_t)(ks * 256) * NHS + c;
    for (int k = 0; k < 256; k += 4) {
        float w0 = Wc[(size_t)(k+0) * NHS];
        float w1 = Wc[(size_t)(k+1) * NHS];
        float w2 = Wc[(size_t)(k+2) * NHS];
        float w3 = Wc[(size_t)(k+3) * NHS];
#pragma unroll
        for (int r = 0; r < 32; r++) {
            float4 xv = *reinterpret_cast<const float4*>(&xs[r][k]);
            acc[r] += xv.x * w0 + xv.y * w1 + xv.z * w2 + xv.w * w3;
        }
    }
#pragma unroll
    for (int r = 0; r < 32; r++)
        g_qpart[((size_t)ks * MQ + r0 + r) * NHS + c] = acc[r];
}

// ---------------- reduce + RoPE -> g_Qp ----------------------------------------
__global__ void __launch_bounds__(256) rope_reduce(const int* __restrict__ pos32)
{
    __shared__ float qrow[NHS];
    __shared__ int is64;
    int row = blockIdx.x, t = threadIdx.x;
    if (t == 0) {
        int f = 0;
        for (int i = 1; i < 256; i += 2) f |= pos32[i];
        is64 = (f == 0) ? 1 : 0;
    }
#pragma unroll
    for (int j = 0; j < 4; j++) {
        int c = j * 256 + t;
        float s = 0.f;
#pragma unroll
        for (int ks = 0; ks < KSPL; ks++)
            s += g_qpart[((size_t)ks * MQ + row) * NHS + c];
        qrow[c] = s;
    }
    __syncthreads();
    int p = is64 ? pos32[2 * row] : pos32[row];
    float pf = (float)p;
#pragma unroll
    for (int j = 0; j < 4; j++) {
        int c = j * 256 + t;
        int d = c & 63, fi = d & 31;
        float invf = (float)pow(10000.0, -(double)fi / 32.0);
        float sv, cv;
        sincosf(pf * invf, &sv, &cv);
        float rot = (d & 32) ? qrow[c - 32] : -qrow[c + 32];
        g_Qp[(size_t)row * NHS + c] = qrow[c] * cv + rot * sv;
    }
}

// ---------------- q~ = q_head @ Wk_head^T, scaled 0.125, fp16 ------------------
// grid (128 bh, 8 col-chunks), 256 threads
__global__ void __launch_bounds__(256) qtilde(const float* __restrict__ Wk)
{
    int bh = blockIdx.x, b = bh >> 4, h = bh & 15;
    int c0 = blockIdx.y * 128;
    __shared__ float qs[32][65];
    __shared__ float wks[128][65];
    int t = threadIdx.x;
    for (int i = t; i < 32 * 64; i += 256) {
        int q = i >> 6, d = i & 63;
        qs[q][d] = g_Qp[(size_t)(b * NLQ + q) * NHS + h * ND + d];
    }
    for (int i = t; i < 128 * 64; i += 256) {
        int r = i >> 6, d = i & 63;
        wks[r][d] = Wk[(size_t)(c0 + r) * NHS + h * ND + d];
    }
    __syncthreads();
    int cl = t & 127, qg = t >> 7;   // qg 0..1 -> 16 q each
    float acc[16];
#pragma unroll
    for (int j = 0; j < 16; j++) acc[j] = 0.f;
#pragma unroll
    for (int d = 0; d < 64; d++) {
        float w = wks[cl][d];
#pragma unroll
        for (int j = 0; j < 16; j++) acc[j] += qs[qg * 16 + j][d] * w;
    }
#pragma unroll
    for (int j = 0; j < 16; j++) {
        int m = bh * NLQ + qg * 16 + j;
        g_Qt[(size_t)m * NHS + c0 + cl] = __float2half_rn(acc[j] * 0.125f);
    }
}

// ---------------- S = q~ @ X^T (wmma 64x64 warp tiles, 128 thr) -----------------
// grid (32 n-tiles, 4 m-tiles, 8 b)
#define BM 128
#define BN 128
#define BK 32
#define APAD 8
__global__ void __launch_bounds__(128) sgemm()
{
    int b = blockIdx.z;
    int n0 = blockIdx.x * BN, m0 = blockIdx.y * BM;
    const __half* Ab = g_Qt + (size_t)b * 512 * NHS;
    const __half* Xb = g_Xh + (size_t)b * NLKV * NHS;
    float* Cb = g_S + (size_t)b * 512 * NLKV;

    __shared__ __align__(16) __half As[2][BM][BK + APAD];   // 2 x 10240 B
    __shared__ __align__(16) __half Bs[2][BN][BK + APAD];   // 2 x 10240 B (col tile)

    int t = threadIdx.x, wid = t >> 5;
    int wm = wid & 1, wn = wid >> 1;   // 2 x 2 warps of 64x64

    wmma::fragment<wmma::accumulator, 16, 16, 16, float> cf[4][4];
#pragma unroll
    for (int i = 0; i < 4; i++)
#pragma unroll
        for (int j = 0; j < 4; j++) wmma::fill_fragment(cf[i][j], 0.f);

    auto load_stage = [&](int it, int buf) {
        int k0 = it * BK;
#pragma unroll
        for (int ch = t; ch < 512; ch += 128) {
            int r = ch >> 2, c = ch & 3;
            cp_async16(smem_u32(&As[buf][r][c * 8]),
                       &Ab[(size_t)(m0 + r) * NHS + k0 + c * 8]);
        }
#pragma unroll
        for (int ch = t; ch < 512; ch += 128) {
            int r = ch >> 2, c = ch & 3;
            cp_async16(smem_u32(&Bs[buf][r][c * 8]),
                       &Xb[(size_t)(n0 + r) * NHS + k0 + c * 8]);
        }
        CP_COMMIT();
    };

    load_stage(0, 0);
    const int NIT = NHS / BK;   // 32
    for (int it = 0; it < NIT; it++) {
        int buf = it & 1;
        if (it + 1 < NIT) { load_stage(it + 1, buf ^ 1); CP_WAIT1(); }
        else              { CP_WAIT0(); }
        __syncthreads();
#pragma unroll
        for (int kk = 0; kk < BK; kk += 16) {
            wmma::fragment<wmma::matrix_a, 16, 16, 16, __half, wmma::row_major> af[4];
#pragma unroll
            for (int i = 0; i < 4; i++)
                wmma::load_matrix_sync(af[i], &As[buf][wm * 64 + i * 16][kk], BK + APAD);
#pragma unroll
            for (int j = 0; j < 4; j++) {
                wmma::fragment<wmma::matrix_b, 16, 16, 16, __half, wmma::col_major> bf;
                wmma::load_matrix_sync(bf, &Bs[buf][wn * 64 + j * 16][kk], BK + APAD);
#pragma unroll
                for (int i = 0; i < 4; i++)
                    wmma::mma_sync(cf[i][j], af[i], bf, cf[i][j]);
            }
        }
        __syncthreads();
    }
#pragma unroll
    for (int i = 0; i < 4; i++)
#pragma unroll
        for (int j = 0; j < 4; j++)
            wmma::store_matrix_sync(
                &Cb[(size_t)(m0 + wm * 64 + i * 16) * NLKV + n0 + wn * 64 + j * 16],
                cf[i][j], NLKV, wmma::mem_row_major);
}

// ---------------- softmax rows of 4096 -> fp16 P --------------------------------
__global__ void __launch_bounds__(256) softmax_rows()
{
    size_t m = blockIdx.x;
    const float* row = g_S + m * NLKV;
    __half* prow = g_P + m * NLKV;
    int t = threadIdx.x;
    __shared__ float red[8];

    float x[16];
    float mx = -1e30f;
#pragma unroll
    for (int i = 0; i < 16; i++) {
        x[i] = row[i * 256 + t];
        mx = fmaxf(mx, x[i]);
    }
#pragma unroll
    for (int o = 16; o > 0; o >>= 1)
        mx = fmaxf(mx, __shfl_xor_sync(0xffffffffu, mx, o));
    if ((t & 31) == 0) red[t >> 5] = mx;
    __syncthreads();
    if (t < 8) {
        float v = red[t];
#pragma unroll
        for (int o = 4; o > 0; o >>= 1) v = fmaxf(v, __shfl_xor_sync(0xffu, v, o));
        red[t] = v;
    }
    __syncthreads();
    mx = red[0];

    float s = 0.f;
#pragma unroll
    for (int i = 0; i < 16; i++) {
        x[i] = __expf(x[i] - mx);
        s += x[i];
    }
#pragma unroll
    for (int o = 16; o > 0; o >>= 1)
        s += __shfl_xor_sync(0xffffffffu, s, o);
    __syncthreads();
    if ((t & 31) == 0) red[t >> 5] = s;
    __syncthreads();
    if (t < 8) {
        float v = red[t];
#pragma unroll
        for (int o = 4; o > 0; o >>= 1) v += __shfl_xor_sync(0xffu, v, o);
        red[t] = v;
    }
    __syncthreads();
    float inv = 1.f / red[0];
#pragma unroll
    for (int i = 0; i < 16; i++)
        prow[i * 256 + t] = __float2half_rn(x[i] * inv);
}

// ---------------- Y = P @ X (wmma 64x64 warp tiles, 128 thr) --------------------
// grid (8 n-tiles, 4 m-tiles, 8 b)
#define BPAD 8
__global__ void __launch_bounds__(128) ygemm()
{
    int b = blockIdx.z;
    int n0 = blockIdx.x * BN, m0 = blockIdx.y * BM;
    const __half* Ab = g_P + (size_t)b * 512 * NLKV;
    const __half* Xb = g_Xh + (size_t)b * NLKV * NHS;
    float* Cb = g_Y + (size_t)b * 512 * NHS;

    __shared__ __align__(16) __half As[2][BM][BK + APAD];   // 2 x 10240 B
    __shared__ __align__(16) __half Bs[2][BK][BN + BPAD];   // 2 x  8704 B

    int t = threadIdx.x, wid = t >> 5;
    int wm = wid & 1, wn = wid >> 1;

    wmma::fragment<wmma::accumulator, 16, 16, 16, float> cf[4][4];
#pragma unroll
    for (int i = 0; i < 4; i++)
#pragma unroll
        for (int j = 0; j < 4; j++) wmma::fill_fragment(cf[i][j], 0.f);

    auto load_stage = [&](int it, int buf) {
        int k0 = it * BK;
#pragma unroll
        for (int ch = t; ch < 512; ch += 128) {
            int r = ch >> 2, c = ch & 3;
            cp_async16(smem_u32(&As[buf][r][c * 8]),
                       &Ab[(size_t)(m0 + r) * NLKV + k0 + c * 8]);
        }
#pragma unroll
        for (int ch = t; ch < 512; ch += 128) {
            int r = ch >> 4, c = ch & 15;
            cp_async16(smem_u32(&Bs[buf][r][c * 8]),
                       &Xb[(size_t)(k0 + r) * NHS + n0 + c * 8]);
        }
        CP_COMMIT();
    };

    load_stage(0, 0);
    const int NIT = NLKV / BK;   // 128
    for (int it = 0; it < NIT; it++) {
        int buf = it & 1;
        if (it + 1 < NIT) { load_stage(it + 1, buf ^ 1); CP_WAIT1(); }
        else              { CP_WAIT0(); }
        __syncthreads();
#pragma unroll
        for (int kk = 0; kk < BK; kk += 16) {
            wmma::fragment<wmma::matrix_a, 16, 16, 16, __half, wmma::row_major> af[4];
#pragma unroll
            for (int i = 0; i < 4; i++)
                wmma::load_matrix_sync(af[i], &As[buf][wm * 64 + i * 16][kk], BK + APAD);
#pragma unroll
            for (int j = 0; j < 4; j++) {
                wmma::fragment<wmma::matrix_b, 16, 16, 16, __half, wmma::row_major> bf;
                wmma::load_matrix_sync(bf, &Bs[buf][kk][wn * 64 + j * 16], BN + BPAD);
#pragma unroll
                for (int i = 0; i < 4; i++)
                    wmma::mma_sync(cf[i][j], af[i], bf, cf[i][j]);
            }
        }
        __syncthreads();
    }
#pragma unroll
    for (int i = 0; i < 4; i++)
#pragma unroll
        for (int j = 0; j < 4; j++)
            wmma::store_matrix_sync(
                &Cb[(size_t)(m0 + wm * 64 + i * 16) * NHS + n0 + wn * 64 + j * 16],
                cf[i][j], NHS, wmma::mem_row_major);
}

// ---------------- vproj partials: ctx_head += Y_head[k-range] @ Wv_head ---------
// grid (128 bh, 4 ks), 256 threads; writes g_qpart (reused as vproj partials)
__global__ void __launch_bounds__(256) vproj_part(const float* __restrict__ Wv)
{
    int bh = blockIdx.x, b = bh >> 4, h = bh & 15;
    int ks = blockIdx.y;
    __shared__ float wvs[128][65];
    __shared__ float ys[32][129];
    int t = threadIdx.x;
    int d = t & 63, qg = t >> 6;   // qg 0..3 -> 8 q each
    float acc[8];
#pragma unroll
    for (int j = 0; j < 8; j++) acc[j] = 0.f;

#pragma unroll
    for (int half = 0; half < 2; half++) {
        int c0 = ks * 256 + half * 128;
        __syncthreads();
        for (int i = t; i < 128 * 64; i += 256) {
            int r = i >> 6, dd = i & 63;
            wvs[r][dd] = Wv[(size_t)(c0 + r) * NHS + h * ND + dd];
        }
        for (int i = t; i < 32 * 128; i += 256) {
            int q = i >> 7, cl = i & 127;
            ys[q][cl] = g_Y[(size_t)(bh * NLQ + q) * NHS + c0 + cl];
        }
        __syncthreads();
#pragma unroll 4
        for (int c = 0; c < 128; c++) {
            float w = wvs[c][d];
#pragma unroll
            for (int j = 0; j < 8; j++) acc[j] += ys[qg * 8 + j][c] * w;
        }
    }
#pragma unroll
    for (int j = 0; j < 8; j++)
        g_qpart[((size_t)ks * MQ + b * NLQ + qg * 8 + j) * NHS + h * ND + d] = acc[j];
}

// ---------------- oproj partial (sums vproj partials in the stage load) ---------
// grid (4, 8, 4), 256 threads
__global__ void __launch_bounds__(256) oproj_part(const float* __restrict__ W)
{
    int c0 = blockIdx.x * 256, r0 = blockIdx.y * 32, ks = blockIdx.z;
    __shared__ float xs[32][256];
    int t = threadIdx.x;
    for (int i = t; i < 32 * 256; i += 256) {
        int r = i >> 8, kk = i & 255;
        size_t base = (size_t)(r0 + r) * NHS + ks * 256 + kk;
        float s = 0.f;
#pragma unroll
        for (int s2 = 0; s2 < KSPL; s2++)
            s += g_qpart[(size_t)s2 * MQ * NHS + base];
        xs[r][kk] = s;
    }
    __syncthreads();
    float acc[32];
#pragma unroll
    for (int r = 0; r < 32; r++) acc[r] = 0.f;
    int c = c0 + t;
    const float* Wc = W + (size_t)(ks * 256) * NHS + c;
    for (int k = 0; k < 256; k += 4) {
        float w0 = Wc[(size_t)(k+0) * NHS];
        float w1 = Wc[(size_t)(k+1) * NHS];
        float w2 = Wc[(size_t)(k+2) * NHS];
        float w3 = Wc[(size_t)(k+3) * NHS];
#pragma unroll
        for (int r = 0; r < 32; r++) {
            float4 xv = *reinterpret_cast<const float4*>(&xs[r][k]);
            acc[r] += xv.x * w0 + xv.y * w1 + xv.z * w2 + xv.w * w3;
        }
    }
#pragma unroll
    for (int r = 0; r < 32; r++)
        g_opart[((size_t)ks * MQ + r0 + r) * NHS + c] = acc[r];
}

__global__ void __launch_bounds__(256) oreduce(float* __restrict__ Y)
{
    int i = blockIdx.x * 256 + threadIdx.x;
    float s = 0.f;
#pragma unroll
    for (int ks = 0; ks < KSPL; ks++)
        s += g_opart[(size_t)ks * MQ * NHS + i];
    Y[i] = s;
}

// ================= launcher =======================================================
extern "C" void kernel_launch(void* const* d_in, const int* in_sizes, int n_in,
                              void* d_out, int out_size)
{
    const float* hidden = (const float*)d_in[0];
    const float* enc    = (const float*)d_in[1];
    const int*   pos32  = (const int*)d_in[2];
    const float* Wq     = (const float*)d_in[3];
    const float* Wk     = (const float*)d_in[4];
    const float* Wv     = (const float*)d_in[5];
    const float* Wo     = (const float*)d_in[6];
    float*       out    = (float*)d_out;

    // encoder to fp16
    cvt_enc<<<(MKV * NHS / 4 + 255) / 256, 256>>>(enc, MKV * NHS / 4);

    // Q projection + RoPE
    qproj_part<<<dim3(4, 8, KSPL), 256>>>(hidden, Wq);
    rope_reduce<<<MQ, 256>>>(pos32);

    // fold Wk into q
    qtilde<<<dim3(NB * NH, 8), 256>>>(Wk);

    // S = q~ @ X^T
    sgemm<<<dim3(NLKV / BN, 4, NB), 128>>>();

    // softmax
    softmax_rows<<<MR, 256>>>();

    // Y = P @ X
    ygemm<<<dim3(NHS / BN, 4, NB), 128>>>();

    // fold Wv (partials into g_qpart)
    vproj_part<<<dim3(NB * NH, KSPL), 256>>>(Wv);

    // output projection
    oproj_part<<<dim3(4, 8, KSPL), 256>>>(Wo);
    oreduce<<<(MQ * NHS) / 256, 256>>>(out);
}